// round 11
// baseline (speedup 1.0000x reference)
#include <cuda_runtime.h>
#include <cuda_bf16.h>

// Segment-sum scatter at the LTS/atomic floor, FUSED with output zeroing
// (single graph node; removes memset node + one launch boundary ~2.5us).
//
// Floor model (confirmed R1/R3/R6/R7/R9 at 50.0-50.9us kernel): the LTS
// aggregate binds — 218MB read-through + ~410MB slice-internal atomic RMW
// ~= 12.6TB/s = the ~6300 B/cyc path-independent LTS cap. DRAM moves exactly
// the compulsory 227MB; no SM-side pipe is near saturation. All LTS bytes
// irreducible (16B max RED width, bf16 fails 1e-3, ~0 duplicates on
// uniform-random indices, no L2 bypass on sm_103a).
//
// Fusion protocol (deadlock-free, replay-deterministic):
//   - __launch_bounds__(TPB, 8) pins 8 blocks/SM -> 1184 guaranteed
//     co-resident wave-1 blocks; ZBLKS=512 zeroer blocks (bids 0..511) are
//     all wave-1 resident, so every waiter's dependency is resident.
//   - every block front-batches its 8 loads FIRST (they never touch out4),
//     overlapping the zero phase.
//   - zeroers zero a 782-float4 slice, __threadfence, arrive on g_zero_done.
//   - all blocks poll g_zero_done==ZBLKS (thread 0, acquire + backoff),
//     __syncthreads, then fire the 4 fire-and-forget REDs.
//   - retire counter: last of the 12500 blocks resets both counters to 0
//     -> identical state every graph replay.
//
// Proven-optimal scatter shape: TPB=256, 4 quads/thread grid-strided; warp
// loads 32 consecutive float4s (4x128B lines/LDG.128); 4 lanes share one
// broadcast src int; each edge's 4 RED.E.ADD.F32.V4 lanes cover one 64B
// output line. edge_w streams evict-first (__ldcs).
//
// Fixed sizes: E=3,200,000, F=16 -> 12.8M quads = 3.2M threads x 4.
// Output: 400,000 float4.

#define E_TOTAL   3200000
#define NUM_QUADS (E_TOTAL * 4)
#define TPB       256
#define QPT       4
#define TOTAL_THREADS (NUM_QUADS / QPT)        // 3,200,000
#define NBLK          (TOTAL_THREADS / TPB)    // 12,500

#define OUT_F4    400000
#define ZBLKS     512
#define F4_PER_ZB ((OUT_F4 + ZBLKS - 1) / ZBLKS)   // 782

__device__ unsigned g_zero_done = 0;   // zeroer arrivals
__device__ unsigned g_retired   = 0;   // retired blocks (for counter reset)

__global__ void __launch_bounds__(TPB, 8)
spmm_fused_kernel(const int* __restrict__ src,
                  const float4* __restrict__ w4,   // [E*4] float4
                  float4* __restrict__ out4)       // [N*4] float4
{
    const int tid = blockIdx.x * TPB + threadIdx.x;
    const int S   = TOTAL_THREADS;

    const int i0 = tid;
    const int i1 = tid + S;
    const int i2 = tid + 2 * S;
    const int i3 = tid + 3 * S;

    // ---- Phase 1: front-batched loads (never touch out4; overlap zeroing) --
    int s0 = __ldg(&src[i0 >> 2]);
    int s1 = __ldg(&src[i1 >> 2]);
    int s2 = __ldg(&src[i2 >> 2]);
    int s3 = __ldg(&src[i3 >> 2]);

    float4 v0 = __ldcs(&w4[i0]);
    float4 v1 = __ldcs(&w4[i1]);
    float4 v2 = __ldcs(&w4[i2]);
    float4 v3 = __ldcs(&w4[i3]);

    // ---- Phase 2: zeroers clear their output slice ------------------------
    if (blockIdx.x < ZBLKS) {
        const int base = blockIdx.x * F4_PER_ZB;
        #pragma unroll
        for (int k = 0; k < (F4_PER_ZB + TPB - 1) / TPB; k++) {
            int idx = base + k * TPB + threadIdx.x;
            if (idx < base + F4_PER_ZB && idx < OUT_F4)
                out4[idx] = make_float4(0.f, 0.f, 0.f, 0.f);
        }
        __syncthreads();
        if (threadIdx.x == 0) {
            __threadfence();                    // publish zeros (gpu scope)
            atomicAdd(&g_zero_done, 1u);        // release-ish arrive
        }
    }

    // ---- Phase 3: wait until all ZBLKS slices are zeroed -------------------
    if (threadIdx.x == 0) {
        unsigned done;
        do {
            asm volatile("ld.acquire.gpu.global.u32 %0, [%1];"
                         : "=r"(done) : "l"(&g_zero_done));
            if (done >= ZBLKS) break;
            __nanosleep(128);
        } while (true);
    }
    __syncthreads();   // distribute the acquire to the whole block

    // ---- Phase 4: fire-and-forget vector reduction atomics ----------------
    atomicAdd(&out4[((size_t)s0 << 2) + (i0 & 3)], v0);
    atomicAdd(&out4[((size_t)s1 << 2) + (i1 & 3)], v1);
    atomicAdd(&out4[((size_t)s2 << 2) + (i2 & 3)], v2);
    atomicAdd(&out4[((size_t)s3 << 2) + (i3 & 3)], v3);

    // ---- Phase 5: last block resets counters (replay-deterministic) -------
    if (threadIdx.x == 0) {
        unsigned r = atomicAdd(&g_retired, 1u);
        if (r == NBLK - 1) {
            g_zero_done = 0;
            g_retired   = 0;
            __threadfence();
        }
    }
}

extern "C" void kernel_launch(void* const* d_in, const int* in_sizes, int n_in,
                              void* d_out, int out_size)
{
    const int*   edge   = (const int*)d_in[0];   // edge[0] = src, first E ints
    const float* edge_w = (const float*)d_in[1];

    spmm_fused_kernel<<<NBLK, TPB>>>(
        edge,
        (const float4*)edge_w,
        (float4*)d_out);
}

// round 12
// speedup vs baseline: 1.4512x; 1.4512x over previous
#include <cuda_runtime.h>
#include <cuda_bf16.h>

// FINAL: segment-sum scatter at the LTS/atomic structural floor.
//
// Floor model (confirmed 5x at 50.0-50.9us kernel: R1/R3/R6/R7/R9): the LTS
// aggregate binds — 218MB compulsory read-through + ~410MB slice-internal
// atomic RMW ~= 12.6TB/s = the ~6300 B/cyc path-independent LTS cap. DRAM
// moves exactly the compulsory 227MB at 56-58% of spec; no SM-side pipe is
// near saturation (issue 10%, occ 83%). All LTS bytes irreducible: 16B max
// RED width, bf16 payload fails the 1e-3 budget, ~0 expected duplicates on
// uniform-random indices, no L2 bypass on sm_103a, zeroing mandatory per
// replay (REDs accumulate).
//
// Full lever map (all measured):
//   per-edge 64B loads  -> 81us  (coalescing break, R2)
//   TMA bulk-reduce     -> 71us  (per-op TMA/ALU envelope, R4)
//   TPB=512             -> 69us  (L1tex-queue contention, R5)
//   PDL zero overlap    -> net 0 (contends with saturated LTS, R8)
//   fused zero+gridsync -> 77us  (sync through saturated LTS, R10)
//
// Proven-optimal shape: TPB=256, 4 quads/thread grid-strided by the total
// thread count. Warp loads 32 consecutive float4s = 4 x 128B lines/LDG.128;
// 4 lanes share one broadcast src int; 8 loads front-batched (MLP_p1=8)
// ahead of 4 fire-and-forget RED.E.ADD.F32.V4 (each edge's 4 lanes cover one
// contiguous 64B output line). edge_w streams evict-first (__ldcs) so the
// 6.4MB destination region stays L2-resident for the RMWs.
//
// Fixed sizes: E = 3,200,000, F = 16 -> 12.8M quads = 3.2M threads x 4.

#define E_TOTAL   3200000
#define NUM_QUADS (E_TOTAL * 4)
#define TPB       256
#define QPT       4
#define TOTAL_THREADS (NUM_QUADS / QPT)        // 3,200,000
#define NBLK          (TOTAL_THREADS / TPB)    // 12,500

__global__ void __launch_bounds__(TPB)
spmm_scatter_kernel(const int* __restrict__ src,
                    const float4* __restrict__ w4,   // [E*4] float4
                    float4* __restrict__ out4)       // [N*4] float4
{
    const int tid = blockIdx.x * TPB + threadIdx.x;
    const int S   = TOTAL_THREADS;

    const int i0 = tid;
    const int i1 = tid + S;
    const int i2 = tid + 2 * S;
    const int i3 = tid + 3 * S;

    // Front-batched independent loads (ptxas hoists these together, MLP ~8).
    int s0 = __ldg(&src[i0 >> 2]);
    int s1 = __ldg(&src[i1 >> 2]);
    int s2 = __ldg(&src[i2 >> 2]);
    int s3 = __ldg(&src[i3 >> 2]);

    float4 v0 = __ldcs(&w4[i0]);   // evict-first: edge_w streams once,
    float4 v1 = __ldcs(&w4[i1]);   // keep L2 for the atomic destinations
    float4 v2 = __ldcs(&w4[i2]);
    float4 v3 = __ldcs(&w4[i3]);

    atomicAdd(&out4[((size_t)s0 << 2) + (i0 & 3)], v0);
    atomicAdd(&out4[((size_t)s1 << 2) + (i1 & 3)], v1);
    atomicAdd(&out4[((size_t)s2 << 2) + (i2 & 3)], v2);
    atomicAdd(&out4[((size_t)s3 << 2) + (i3 & 3)], v3);
}

extern "C" void kernel_launch(void* const* d_in, const int* in_sizes, int n_in,
                              void* d_out, int out_size)
{
    const int*   edge   = (const int*)d_in[0];   // edge[0] = src, first E ints
    const float* edge_w = (const float*)d_in[1];

    // d_out poisoned to 0xAA -> zero it (memset node is graph-capturable);
    // also pre-warms the 6.4 MB destination region in L2. Mandatory every
    // replay: REDs accumulate otherwise.
    cudaMemsetAsync(d_out, 0, (size_t)out_size * sizeof(float), 0);

    spmm_scatter_kernel<<<NBLK, TPB>>>(
        edge,
        (const float4*)edge_w,
        (float4*)d_out);
}